// round 1
// baseline (speedup 1.0000x reference)
#include <cuda_runtime.h>

#define BB 8
#define TT 1024
#define DM 1024
#define HS 64
#define NROWS (BB*TT)        // 8192
#define QR_STRIDE 1028       // 1025 padded to multiple of 4
#define MAXREL 1024

// -------- scratch (static device arrays; no runtime allocation) --------
__device__ float g_q[NROWS*HS];
__device__ float g_k[NROWS*HS];
__device__ float g_v[NROWS*HS];
__device__ float g_qr[NROWS*QR_STRIDE];   // QR[b*T+i][p] = q . rel[p], p in [0,1024]
__device__ float g_rk[NROWS*MAXREL];      // RK[b*T+j][c] = k . rel[1024+c], c in [0,1023]
__device__ float g_rr[MAXREL];            // rr[c] = rel[1024+c] . rel[1024-c]

// ============================================================
// Kernel 1: fused QKV projection.  q = xWq + bq, k = xWk + bk, v = xWv
// Block: 64 rows x 192 cols, 256 threads, each thread 4x12.
// ============================================================
__global__ __launch_bounds__(256) void proj_kernel(
    const float* __restrict__ x,
    const float* __restrict__ Wk, const float* __restrict__ bk,
    const float* __restrict__ Wq, const float* __restrict__ bq,
    const float* __restrict__ Wv)
{
    __shared__ float xst[32][65];    // [kk][row]
    __shared__ float wst[32][192];   // [kk][col]  col: 0-63 k, 64-127 q, 128-191 v

    int r0  = blockIdx.x * 64;
    int tid = threadIdx.x;
    int tx  = tid & 15, ty = tid >> 4;

    float acc[4][12];
#pragma unroll
    for (int i = 0; i < 4; i++)
#pragma unroll
        for (int j = 0; j < 12; j++) acc[i][j] = 0.f;

    for (int k0 = 0; k0 < DM; k0 += 32) {
#pragma unroll
        for (int i = 0; i < 8; i++) {
            int idx = tid + i*256;
            int row = idx >> 5, kk = idx & 31;
            xst[kk][row] = x[(r0+row)*DM + k0 + kk];
        }
#pragma unroll
        for (int i = 0; i < 24; i++) {
            int idx = tid + i*256;
            int kk = idx / 192, c = idx - kk*192;
            const float* W = (c < 64) ? Wk : (c < 128 ? Wq : Wv);
            wst[kk][c] = W[(k0+kk)*HS + (c & 63)];
        }
        __syncthreads();
#pragma unroll
        for (int kk = 0; kk < 32; kk++) {
            float a[4], b[12];
#pragma unroll
            for (int i = 0; i < 4; i++)  a[i] = xst[kk][ty*4 + i];
#pragma unroll
            for (int j = 0; j < 12; j++) b[j] = wst[kk][tx*12 + j];
#pragma unroll
            for (int i = 0; i < 4; i++)
#pragma unroll
                for (int j = 0; j < 12; j++) acc[i][j] += a[i]*b[j];
        }
        __syncthreads();
    }

#pragma unroll
    for (int i = 0; i < 4; i++) {
        int row = r0 + ty*4 + i;
#pragma unroll
        for (int j = 0; j < 12; j++) {
            int c = tx*12 + j;
            float v = acc[i][j];
            if (c < 64)       g_k[row*HS + c]        = v + bk[c];
            else if (c < 128) g_q[row*HS + (c-64)]   = v + bq[c-64];
            else              g_v[row*HS + (c-128)]  = v;
        }
    }
}

// ============================================================
// Kernel 2: rr[c] = rel[1024+c] . rel[1024-c]
// ============================================================
__global__ void rr_kernel(const float* __restrict__ rel)
{
    int d = blockIdx.x * 256 + threadIdx.x;
    if (d < MAXREL) {
        const float* a = rel + (size_t)(1024 + d) * HS;
        const float* b = rel + (size_t)(1024 - d) * HS;
        float s = 0.f;
#pragma unroll
        for (int h = 0; h < HS; h++) s += a[h] * b[h];
        g_rr[d] = s;
    }
}

// ============================================================
// Kernel 3: QR / RK precompute GEMMs with causal tile trimming.
// out[row][p] = dot(A[row], rel[relOff + p])
// Block: 64 rows x 128 p, 256 threads, each thread 4x8.
// ============================================================
#define REL_SMEM_FLOATS (64*68 + 64*132)
__global__ __launch_bounds__(256) void rel_gemm_kernel(
    const float* __restrict__ rel, int mode)
{
    extern __shared__ float sm[];
    float* Ast = sm;            // [64][68]   (d-major, transposed)
    float* Rst = sm + 64*68;    // [64][132]  (d-major, transposed)

    int r0 = blockIdx.x * 64;
    int i0 = r0 & (TT - 1);     // position within the batch
    int p0 = blockIdx.y * 128;

    const float* A; float* outp; int relOff, pmax, ostride;
    if (mode == 0) {
        // QR: needed p >= 1024 - i  -> tile needed if p0+127 >= 1024-(i0+63)
        if (p0 + 127 < 1024 - (i0 + 63)) return;
        A = g_q; outp = g_qr; relOff = 0; pmax = 1024; ostride = QR_STRIDE;
    } else {
        // RK: needed c <= 1023 - j  -> tile needed if p0 <= 1023 - j0
        if (p0 > 1023 - i0) return;
        A = g_k; outp = g_rk; relOff = 1024; pmax = 1023; ostride = MAXREL;
    }

    int tid = threadIdx.x, tx = tid & 15, ty = tid >> 4;

#pragma unroll
    for (int i = 0; i < 16; i++) {
        int idx = tid + i*256;
        int row = idx >> 6, d = idx & 63;
        Ast[d*68 + row] = A[(r0+row)*HS + d];
    }
#pragma unroll
    for (int i = 0; i < 32; i++) {
        int idx = tid + i*256;
        int p = idx >> 6, d = idx & 63;
        Rst[d*132 + p] = rel[(size_t)(relOff + p0 + p)*HS + d];
    }
    __syncthreads();

    float acc[4][8];
#pragma unroll
    for (int i = 0; i < 4; i++)
#pragma unroll
        for (int j = 0; j < 8; j++) acc[i][j] = 0.f;

#pragma unroll
    for (int d = 0; d < 64; d++) {
        float4 a4 = *(const float4*)&Ast[d*68 + ty*4];
        float4 r0v = *(const float4*)&Rst[d*132 + tx*8];
        float4 r1v = *(const float4*)&Rst[d*132 + tx*8 + 4];
        float av[4] = {a4.x, a4.y, a4.z, a4.w};
        float rv[8] = {r0v.x, r0v.y, r0v.z, r0v.w, r1v.x, r1v.y, r1v.z, r1v.w};
#pragma unroll
        for (int i = 0; i < 4; i++)
#pragma unroll
            for (int j = 0; j < 8; j++) acc[i][j] += av[i]*rv[j];
    }

#pragma unroll
    for (int i = 0; i < 4; i++) {
        int row = r0 + ty*4 + i;
        int pb  = p0 + tx*8;
        if (pb + 7 <= pmax) {
            *(float4*)&outp[row*ostride + pb] =
                make_float4(acc[i][0], acc[i][1], acc[i][2], acc[i][3]);
            *(float4*)&outp[row*ostride + pb + 4] =
                make_float4(acc[i][4], acc[i][5], acc[i][6], acc[i][7]);
        } else {
#pragma unroll
            for (int j = 0; j < 8; j++)
                if (pb + j <= pmax) outp[row*ostride + pb + j] = acc[i][j];
        }
    }
}

// ============================================================
// Kernel 4: causal flash attention with relative-position biases.
// Block = (b, 64-row tile). 256 threads, 4x4 micro-tiles.
// score = 0.125 * (qk + QR[b,i,j-i+1024] + RK[b,j,i-j] + rr[i-j])
// ============================================================
#define ATTN_SMEM_FLOATS (64*68*2 + 64*64*2 + 64*128 + 128)
__global__ __launch_bounds__(256) void attn_kernel(float* __restrict__ out)
{
    extern __shared__ float sm[];
    float* qst = sm;                 // [64][68] d-major Q
    float* kst = qst + 64*68;        // [64][68] d-major K
    float* vs  = kst + 64*68;        // [64][64] row-major V
    float* ps  = vs  + 64*64;        // [64][64] probabilities
    float* rks = ps  + 64*64;        // [64][128] staged RK band
    float* rrs = rks + 64*128;       // [128]

    int bi = blockIdx.x;
    int b  = bi >> 4, it = bi & 15;
    int i0 = it * 64;
    int rbase = b * TT;
    int tid = threadIdx.x, tx = tid & 15, ty = tid >> 4;

#pragma unroll
    for (int i = 0; i < 16; i++) {
        int idx = tid + i*256;
        int ii = idx >> 6, d = idx & 63;
        qst[d*68 + ii] = g_q[(rbase + i0 + ii)*HS + d];
    }

    float m[4], l[4], O[4][4];
#pragma unroll
    for (int a = 0; a < 4; a++) {
        m[a] = -1e30f; l[a] = 0.f;
#pragma unroll
        for (int d = 0; d < 4; d++) O[a][d] = 0.f;
    }

    for (int jt = 0; jt <= it; jt++) {
        int j0 = jt * 64;
        __syncthreads();   // protect smem reuse from previous iteration

        // --- stage K, V, RK band, rr band ---
#pragma unroll
        for (int i = 0; i < 16; i++) {
            int idx = tid + i*256;
            int jj = idx >> 6, d = idx & 63;
            kst[d*68 + jj] = g_k[(rbase + j0 + jj)*HS + d];
            vs[jj*64 + d]  = g_v[(rbase + j0 + jj)*HS + d];
        }
        int cbase = i0 - j0 - 63;
#pragma unroll
        for (int i = 0; i < 32; i++) {
            int idx = tid + i*256;
            int jj = idx >> 7, cc = idx & 127;
            int c = cbase + cc;
            float v = 0.f;
            if (cc < 127 && c >= 0 && c < MAXREL)
                v = g_rk[(rbase + j0 + jj)*MAXREL + c];
            rks[jj*128 + cc] = v;
        }
        if (tid < 128) {
            int c = cbase + tid;
            rrs[tid] = (tid < 127 && c >= 0 && c < MAXREL) ? g_rr[c] : 0.f;
        }
        __syncthreads();

        // --- S = Q K^T ---
        float S[4][4];
#pragma unroll
        for (int a = 0; a < 4; a++)
#pragma unroll
            for (int j = 0; j < 4; j++) S[a][j] = 0.f;

#pragma unroll
        for (int d = 0; d < 64; d++) {
            float4 q4 = *(const float4*)&qst[d*68 + ty*4];
            float4 k4 = *(const float4*)&kst[d*68 + tx*4];
            float qa[4] = {q4.x, q4.y, q4.z, q4.w};
            float kb[4] = {k4.x, k4.y, k4.z, k4.w};
#pragma unroll
            for (int a = 0; a < 4; a++)
#pragma unroll
                for (int j = 0; j < 4; j++) S[a][j] += qa[a]*kb[j];
        }

        // --- add relative biases, scale, mask ---
#pragma unroll
        for (int a = 0; a < 4; a++) {
            int ii = ty*4 + a;
            int i  = i0 + ii;
            const float* qrrow = &g_qr[(rbase + i)*QR_STRIDE + (j0 - i + 1024)];
#pragma unroll
            for (int bj = 0; bj < 4; bj++) {
                int jj = tx*4 + bj;
                int j  = j0 + jj;
                if (j <= i) {
                    float s = S[a][bj];
                    s += qrrow[jj];                     // q . rel[j-i+1024]
                    s += rks[jj*128 + (ii - jj + 63)];  // k . rel[i-j+1024]
                    s += rrs[ii - jj + 63];             // rr[i-j]
                    S[a][bj] = s * 0.125f;
                } else {
                    S[a][bj] = -1e30f;
                }
            }
        }

        // --- online softmax (reduce across the 16 tx lanes) ---
#pragma unroll
        for (int a = 0; a < 4; a++) {
            float rm = fmaxf(fmaxf(S[a][0], S[a][1]), fmaxf(S[a][2], S[a][3]));
#pragma unroll
            for (int msk = 1; msk < 16; msk <<= 1)
                rm = fmaxf(rm, __shfl_xor_sync(0xffffffffu, rm, msk));
            float mnew = fmaxf(m[a], rm);
            float corr = __expf(m[a] - mnew);
            float rs = 0.f;
#pragma unroll
            for (int bj = 0; bj < 4; bj++) {
                float p = __expf(S[a][bj] - mnew);
                S[a][bj] = p;
                rs += p;
            }
#pragma unroll
            for (int msk = 1; msk < 16; msk <<= 1)
                rs += __shfl_xor_sync(0xffffffffu, rs, msk);
            l[a] = l[a]*corr + rs;
            m[a] = mnew;
#pragma unroll
            for (int d = 0; d < 4; d++) O[a][d] *= corr;
        }

        // --- stage P, then O += P V ---
#pragma unroll
        for (int a = 0; a < 4; a++)
            *(float4*)&ps[(ty*4 + a)*64 + tx*4] =
                make_float4(S[a][0], S[a][1], S[a][2], S[a][3]);
        __syncthreads();

#pragma unroll
        for (int jj = 0; jj < 64; jj++) {
            float4 v4 = *(const float4*)&vs[jj*64 + tx*4];
#pragma unroll
            for (int a = 0; a < 4; a++) {
                float p = ps[(ty*4 + a)*64 + jj];
                O[a][0] += p*v4.x; O[a][1] += p*v4.y;
                O[a][2] += p*v4.z; O[a][3] += p*v4.w;
            }
        }
    }

    // --- epilogue ---
#pragma unroll
    for (int a = 0; a < 4; a++) {
        float inv = 1.f / l[a];
        int i = i0 + ty*4 + a;
        *(float4*)&out[(rbase + i)*HS + tx*4] =
            make_float4(O[a][0]*inv, O[a][1]*inv, O[a][2]*inv, O[a][3]*inv);
    }
}

// ============================================================
extern "C" void kernel_launch(void* const* d_in, const int* in_sizes, int n_in,
                              void* d_out, int out_size)
{
    const float* x   = (const float*)d_in[0];
    const float* Wk  = (const float*)d_in[1];
    const float* bk  = (const float*)d_in[2];
    const float* Wq  = (const float*)d_in[3];
    const float* bq  = (const float*)d_in[4];
    const float* Wv  = (const float*)d_in[5];
    const float* rel = (const float*)d_in[6];
    float* out = (float*)d_out;

    static int attr_done = 0;
    if (!attr_done) {
        cudaFuncSetAttribute(rel_gemm_kernel,
                             cudaFuncAttributeMaxDynamicSharedMemorySize,
                             REL_SMEM_FLOATS * (int)sizeof(float));
        cudaFuncSetAttribute(attn_kernel,
                             cudaFuncAttributeMaxDynamicSharedMemorySize,
                             ATTN_SMEM_FLOATS * (int)sizeof(float));
        attr_done = 1;
    }

    proj_kernel<<<NROWS/64, 256>>>(x, Wk, bk, Wq, bq, Wv);
    rr_kernel<<<4, 256>>>(rel);
    rel_gemm_kernel<<<dim3(NROWS/64, 9), 256, REL_SMEM_FLOATS*sizeof(float)>>>(rel, 0);
    rel_gemm_kernel<<<dim3(NROWS/64, 8), 256, REL_SMEM_FLOATS*sizeof(float)>>>(rel, 1);
    attn_kernel<<<BB*16, 256, ATTN_SMEM_FLOATS*sizeof(float)>>>(out);
}

// round 3
// speedup vs baseline: 1.3939x; 1.3939x over previous
#include <cuda_runtime.h>
#include <cuda_bf16.h>
#include <cstdint>

#define BB 8
#define TT 1024
#define DM 1024
#define HS 64
#define NROWS (BB*TT)        // 8192
#define QR_STRIDE 1028
#define MAXREL 1024

// -------- scratch (static device arrays; no runtime allocation) --------
__device__ float g_q[NROWS*HS];
__device__ float g_k[NROWS*HS];
__device__ float g_v[NROWS*HS];
__device__ float g_qr[(size_t)NROWS*QR_STRIDE];
__device__ float g_rk[(size_t)NROWS*MAXREL];
__device__ float g_rr[MAXREL];
__device__ __nv_bfloat16 g_qs[NROWS*128];      // q split: [row][0:64)=hi, [64:128)=lo
__device__ __nv_bfloat16 g_ks[NROWS*128];      // k split
__device__ __nv_bfloat16 g_rels[2049*128];     // rel split: [p][0:64)=hi, [64:128)=lo
__device__ __nv_bfloat16 g_wt[3*64*2048];      // W^T split: [o][n][0:1024)=hi, [1024:2048)=lo

// ============================================================
// helpers
// ============================================================
__device__ __forceinline__ uint32_t smem_to_u32(const void* p) {
    uint32_t a;
    asm("{ .reg .u64 tmp; cvta.to.shared.u64 tmp, %1; cvt.u32.u64 %0, tmp; }"
        : "=r"(a) : "l"(p));
    return a;
}
__device__ __forceinline__ void ldsm4(uint32_t& r0, uint32_t& r1, uint32_t& r2,
                                      uint32_t& r3, uint32_t addr) {
    asm volatile("ldmatrix.sync.aligned.m8n8.x4.shared.b16 {%0,%1,%2,%3}, [%4];"
        : "=r"(r0), "=r"(r1), "=r"(r2), "=r"(r3) : "r"(addr));
}
__device__ __forceinline__ void mma16816(float* c, const uint32_t* a,
                                         uint32_t b0, uint32_t b1) {
    asm volatile(
        "mma.sync.aligned.m16n8k16.row.col.f32.bf16.bf16.f32 "
        "{%0,%1,%2,%3}, {%4,%5,%6,%7}, {%8,%9}, {%0,%1,%2,%3};"
        : "+f"(c[0]), "+f"(c[1]), "+f"(c[2]), "+f"(c[3])
        : "r"(a[0]), "r"(a[1]), "r"(a[2]), "r"(a[3]), "r"(b0), "r"(b1));
}
__device__ __forceinline__ void split2(float v, __nv_bfloat16& h, __nv_bfloat16& l) {
    h = __float2bfloat16(v);
    l = __float2bfloat16(v - __bfloat162float(h));
}
__device__ __forceinline__ uint32_t pack2(__nv_bfloat16 a, __nv_bfloat16 b) {
    __nv_bfloat162 t; t.x = a; t.y = b;
    return *reinterpret_cast<uint32_t*>(&t);
}

// ============================================================
// Conversion kernels
// ============================================================
__global__ void wsplit_kernel(const float* __restrict__ Wk,
                              const float* __restrict__ Wq,
                              const float* __restrict__ Wv)
{
    int idx = blockIdx.x * 256 + threadIdx.x;
    if (idx >= 3*1024*64) return;
    int o = idx >> 16;
    int r = idx & 65535;
    int kk = r >> 6, n = r & 63;
    const float* W = (o == 0) ? Wk : (o == 1 ? Wq : Wv);
    float v = W[kk*64 + n];
    __nv_bfloat16 h, l; split2(v, h, l);
    g_wt[o*131072 + n*2048 + kk]        = h;
    g_wt[o*131072 + n*2048 + 1024 + kk] = l;
}

__global__ void relsplit_kernel(const float* __restrict__ rel)
{
    int idx = blockIdx.x * 256 + threadIdx.x;
    if (idx >= 2049*64) return;
    int p = idx >> 6, d = idx & 63;
    float v = rel[(size_t)p*64 + d];
    __nv_bfloat16 h, l; split2(v, h, l);
    g_rels[p*128 + d]      = h;
    g_rels[p*128 + 64 + d] = l;
}

__global__ void rr_kernel(const float* __restrict__ rel)
{
    int d = blockIdx.x * 256 + threadIdx.x;
    if (d < MAXREL) {
        const float* a = rel + (size_t)(1024 + d) * HS;
        const float* b = rel + (size_t)(1024 - d) * HS;
        float s = 0.f;
#pragma unroll
        for (int h = 0; h < HS; h++) s += a[h] * b[h];
        g_rr[d] = s;
    }
}

// ============================================================
// Projection GEMM (mma.sync bf16 split): out = x @ W (+bias)
// grid (128 rowtiles, 3 outputs), 128 threads, CTA tile 64x64.
// ============================================================
#define PROJ_SMEM_BYTES (4*64*72*2)    // 36864
__global__ __launch_bounds__(128) void proj_mma_kernel(
    const float* __restrict__ x,
    const float* __restrict__ bk, const float* __restrict__ bq)
{
    extern __shared__ char smc[];
    __nv_bfloat16* Ah = (__nv_bfloat16*)smc;        // [64][72]
    __nv_bfloat16* Al = Ah + 64*72;
    __nv_bfloat16* Bh = Al + 64*72;
    __nv_bfloat16* Bl = Bh + 64*72;
    uint32_t sb = smem_to_u32(smc);
    const uint32_t sAh = sb, sAl = sb + 64*72*2, sBh = sb + 2*64*72*2, sBl = sb + 3*64*72*2;

    int tid = threadIdx.x, wid = tid >> 5, lane = tid & 31;
    int r0 = blockIdx.x * 64;
    int o  = blockIdx.y;
    const __nv_bfloat16* wt = g_wt + (size_t)o * 131072;
    int wm = wid >> 1, wn = wid & 1;     // 2x2 warp grid, 32x32 warp tile

    float c[2][4][4];
#pragma unroll
    for (int mt = 0; mt < 2; mt++)
#pragma unroll
        for (int nt = 0; nt < 4; nt++)
#pragma unroll
            for (int e = 0; e < 4; e++) c[mt][nt][e] = 0.f;

    int lr   = lane & 15;                       // A: row within m16
    int lca  = (lane >> 4) << 3;                // A: k offset 0/8
    int brow = (lane & 7) + ((lane >> 4) << 3); // B: n-row offset within 16
    int bcol = (lane & 8) ? 8 : 0;              // B: k offset 0/8

    for (int ch = 0; ch < 16; ch++) {
        int k0 = ch * 64;
        __syncthreads();
#pragma unroll
        for (int i = 0; i < 16; i++) {
            int idx = tid + i*128;
            int row = idx >> 5, kp = idx & 31;
            float2 v = *(const float2*)&x[(size_t)(r0+row)*1024 + k0 + kp*2];
            __nv_bfloat16 h0,l0,h1,l1;
            split2(v.x,h0,l0); split2(v.y,h1,l1);
            *(uint32_t*)&Ah[row*72 + kp*2] = pack2(h0,h1);
            *(uint32_t*)&Al[row*72 + kp*2] = pack2(l0,l1);
        }
#pragma unroll
        for (int i = 0; i < 16; i++) {
            int idx = tid + i*128;
            int n = idx >> 5, kp = idx & 31;
            *(uint32_t*)&Bh[n*72 + kp*2] = *(const uint32_t*)&wt[n*2048 + k0 + kp*2];
            *(uint32_t*)&Bl[n*72 + kp*2] = *(const uint32_t*)&wt[n*2048 + 1024 + k0 + kp*2];
        }
        __syncthreads();
#pragma unroll
        for (int ks = 0; ks < 4; ks++) {
            int kk = ks * 16;
            uint32_t ah[2][4], al[2][4];
#pragma unroll
            for (int mt = 0; mt < 2; mt++) {
                uint32_t ar = (uint32_t)((wm*32 + mt*16 + lr)*72 + kk + lca) * 2;
                ldsm4(ah[mt][0],ah[mt][1],ah[mt][2],ah[mt][3], sAh + ar);
                ldsm4(al[mt][0],al[mt][1],al[mt][2],al[mt][3], sAl + ar);
            }
#pragma unroll
            for (int p = 0; p < 2; p++) {
                uint32_t br = (uint32_t)((wn*32 + p*16 + brow)*72 + kk + bcol) * 2;
                uint32_t bh[4], bl[4];
                ldsm4(bh[0],bh[1],bh[2],bh[3], sBh + br);
                ldsm4(bl[0],bl[1],bl[2],bl[3], sBl + br);
#pragma unroll
                for (int mt = 0; mt < 2; mt++) {
                    mma16816(c[mt][2*p],   ah[mt], bh[0], bh[1]);
                    mma16816(c[mt][2*p+1], ah[mt], bh[2], bh[3]);
                    mma16816(c[mt][2*p],   al[mt], bh[0], bh[1]);
                    mma16816(c[mt][2*p+1], al[mt], bh[2], bh[3]);
                    mma16816(c[mt][2*p],   ah[mt], bl[0], bl[1]);
                    mma16816(c[mt][2*p+1], ah[mt], bl[2], bl[3]);
                }
            }
        }
    }

    // ---- epilogue: stage to smem, then coalesced stores + split write ----
    __syncthreads();
    float* Cs = (float*)smc;   // [64][68], 17.4KB (overlaps Ah/Al, OK post-sync)
    int g = lane >> 2, lc2 = (lane & 3)*2;
#pragma unroll
    for (int mt = 0; mt < 2; mt++)
#pragma unroll
        for (int nt = 0; nt < 4; nt++) {
            int rrow = wm*32 + mt*16 + g;
            int col  = wn*32 + nt*8 + lc2;
            *(float2*)&Cs[rrow*68 + col]     = make_float2(c[mt][nt][0], c[mt][nt][1]);
            *(float2*)&Cs[(rrow+8)*68 + col] = make_float2(c[mt][nt][2], c[mt][nt][3]);
        }
    __syncthreads();
    const float* bias = (o == 0) ? bk : (o == 1 ? bq : nullptr);
    float* fout = (o == 0) ? g_k : (o == 1 ? g_q : g_v);
    __nv_bfloat16* sout = (o == 0) ? g_ks : (o == 1 ? g_qs : nullptr);
#pragma unroll
    for (int i = 0; i < 32; i++) {
        int idx = tid + i*128;
        int row = idx >> 6, col = idx & 63;
        float v = Cs[row*68 + col];
        if (bias) v += bias[col];
        fout[(size_t)(r0+row)*64 + col] = v;
        if (sout) {
            __nv_bfloat16 h, l; split2(v, h, l);
            sout[(size_t)(r0+row)*128 + col]      = h;
            sout[(size_t)(r0+row)*128 + 64 + col] = l;
        }
    }
}

// ============================================================
// QR / RK GEMM (mma.sync bf16 split): out[row][p] = A[row] . rel[relOff+p]
// grid (64 rowtiles, 9|8 coltiles) trimmed, 256 threads, CTA 128x128, K=64.
// ============================================================
#define QRK_SMEM_BYTES (4*128*72*2)    // 73728
__global__ __launch_bounds__(256) void relgemm_mma_kernel(int mode)
{
    int r0 = blockIdx.x * 128;
    int i0 = r0 & (TT - 1);
    int p0 = blockIdx.y * 128;
    if (mode == 0) { if (p0 + 127 < 1024 - (i0 + 127)) return; }
    else           { if (p0 > 1023 - i0) return; }

    extern __shared__ char smc[];
    __nv_bfloat16* Ah = (__nv_bfloat16*)smc;        // [128][72]
    __nv_bfloat16* Al = Ah + 128*72;
    __nv_bfloat16* Bh = Al + 128*72;
    __nv_bfloat16* Bl = Bh + 128*72;
    uint32_t sb = smem_to_u32(smc);
    const uint32_t sAh = sb, sAl = sb + 128*72*2, sBh = sb + 2*128*72*2, sBl = sb + 3*128*72*2;

    int tid = threadIdx.x, wid = tid >> 5, lane = tid & 31;
    const __nv_bfloat16* A = mode ? g_ks : g_qs;
    const __nv_bfloat16* R = g_rels + (mode ? 1024*128 : 0);

    int wm = wid >> 2, wn = wid & 3;   // 2x4 warp grid, 64x32 warp tile

    float c[4][4][4];
#pragma unroll
    for (int mt = 0; mt < 4; mt++)
#pragma unroll
        for (int nt = 0; nt < 4; nt++)
#pragma unroll
            for (int e = 0; e < 4; e++) c[mt][nt][e] = 0.f;

    // load tiles
#pragma unroll
    for (int i = 0; i < 16; i++) {
        int idx = tid + i*256;         // 4096 u32 = 128 rows x 32 u32
        int row = idx >> 5, kp = idx & 31;
        *(uint32_t*)&Ah[row*72 + kp*2] = *(const uint32_t*)&A[(size_t)(r0+row)*128 + kp*2];
        *(uint32_t*)&Al[row*72 + kp*2] = *(const uint32_t*)&A[(size_t)(r0+row)*128 + 64 + kp*2];
        *(uint32_t*)&Bh[row*72 + kp*2] = *(const uint32_t*)&R[(size_t)(p0+row)*128 + kp*2];
        *(uint32_t*)&Bl[row*72 + kp*2] = *(const uint32_t*)&R[(size_t)(p0+row)*128 + 64 + kp*2];
    }
    __syncthreads();

    int lr   = lane & 15;
    int lca  = (lane >> 4) << 3;
    int brow = (lane & 7) + ((lane >> 4) << 3);
    int bcol = (lane & 8) ? 8 : 0;

#pragma unroll
    for (int ks = 0; ks < 4; ks++) {
        int kk = ks * 16;
        uint32_t ah[4][4], al[4][4];
#pragma unroll
        for (int mt = 0; mt < 4; mt++) {
            uint32_t ar = (uint32_t)((wm*64 + mt*16 + lr)*72 + kk + lca) * 2;
            ldsm4(ah[mt][0],ah[mt][1],ah[mt][2],ah[mt][3], sAh + ar);
            ldsm4(al[mt][0],al[mt][1],al[mt][2],al[mt][3], sAl + ar);
        }
#pragma unroll
        for (int p = 0; p < 2; p++) {
            uint32_t br = (uint32_t)((wn*32 + p*16 + brow)*72 + kk + bcol) * 2;
            uint32_t bh[4], bl[4];
            ldsm4(bh[0],bh[1],bh[2],bh[3], sBh + br);
            ldsm4(bl[0],bl[1],bl[2],bl[3], sBl + br);
#pragma unroll
            for (int mt = 0; mt < 4; mt++) {
                mma16816(c[mt][2*p],   ah[mt], bh[0], bh[1]);
                mma16816(c[mt][2*p+1], ah[mt], bh[2], bh[3]);
                mma16816(c[mt][2*p],   al[mt], bh[0], bh[1]);
                mma16816(c[mt][2*p+1], al[mt], bh[2], bh[3]);
                mma16816(c[mt][2*p],   ah[mt], bl[0], bl[1]);
                mma16816(c[mt][2*p+1], ah[mt], bl[2], bl[3]);
            }
        }
    }

    // ---- epilogue: stage to smem [128][132], trimmed coalesced copy ----
    __syncthreads();
    float* Cs = (float*)smc;   // 67584 B <= 73728
    int g = lane >> 2, lc2 = (lane & 3)*2;
#pragma unroll
    for (int mt = 0; mt < 4; mt++)
#pragma unroll
        for (int nt = 0; nt < 4; nt++) {
            int rrow = wm*64 + mt*16 + g;
            int col  = wn*32 + nt*8 + lc2;
            *(float2*)&Cs[rrow*132 + col]     = make_float2(c[mt][nt][0], c[mt][nt][1]);
            *(float2*)&Cs[(rrow+8)*132 + col] = make_float2(c[mt][nt][2], c[mt][nt][3]);
        }
    __syncthreads();

    int pmax = mode ? 1023 : 1024;
    float* outp = mode ? g_rk : g_qr;
    int ostride = mode ? 1024 : QR_STRIDE;
#pragma unroll
    for (int i = 0; i < 64; i++) {
        int idx = tid + i*256;
        int row = idx >> 7, cc = idx & 127;
        int p = p0 + cc;
        if (p <= pmax)
            outp[(size_t)(r0+row)*ostride + p] = Cs[row*132 + cc];
    }
}

// ============================================================
// Causal flash attention with relative-position biases (fp32).
// 32-row x 64-col tiles, 128 threads, 4x4 micro-tiles, longest-first.
// ============================================================
#define ATTN_SMEM_FLOATS (64*36 + 64*68 + 64*64 + 32*68 + 64*128 + 128)
__global__ __launch_bounds__(128) void attn_kernel(float* __restrict__ out)
{
    extern __shared__ float sm[];
    float* qst = sm;                 // [64][36] d-major Q (32 rows used)
    float* kst = qst + 64*36;        // [64][68] d-major K
    float* vs  = kst + 64*68;        // [64][64] row-major V
    float* ps  = vs  + 64*64;        // [32][68] probabilities
    float* rks = ps  + 32*68;        // [64][128] staged RK band
    float* rrs = rks + 64*128;       // [128]

    int bid = blockIdx.x;
    int b  = bid >> 5;
    int it = 31 - (bid & 31);        // longest tiles first
    int i0 = it * 32;
    int rbase = b * TT;
    int tid = threadIdx.x, tx = tid & 15, ty = tid >> 4;

#pragma unroll
    for (int i = 0; i < 16; i++) {
        int idx = tid + i*128;
        int ii = idx >> 6, d = idx & 63;
        qst[d*36 + ii] = g_q[(size_t)(rbase + i0 + ii)*HS + d];
    }

    float m[4], l[4], O[4][4];
#pragma unroll
    for (int a = 0; a < 4; a++) {
        m[a] = -1e30f; l[a] = 0.f;
#pragma unroll
        for (int d = 0; d < 4; d++) O[a][d] = 0.f;
    }

    int jmax = it >> 1;
    for (int jt = 0; jt <= jmax; jt++) {
        int j0 = jt * 64;
        __syncthreads();
#pragma unroll
        for (int i = 0; i < 32; i++) {
            int idx = tid + i*128;
            int jj = idx >> 6, d = idx & 63;
            kst[d*68 + jj] = g_k[(size_t)(rbase + j0 + jj)*HS + d];
            vs[jj*64 + d]  = g_v[(size_t)(rbase + j0 + jj)*HS + d];
        }
        int cbase = i0 - j0 - 63;
#pragma unroll
        for (int i = 0; i < 64; i++) {
            int idx = tid + i*128;
            int jj = idx >> 7, cc = idx & 127;
            int c = cbase + cc;
            float v = 0.f;
            if (cc < 95 && c >= 0 && c < MAXREL)
                v = g_rk[(size_t)(rbase + j0 + jj)*MAXREL + c];
            rks[jj*128 + cc] = v;
        }
        {
            int c = cbase + tid;
            rrs[tid] = (tid < 95 && c >= 0 && c < MAXREL) ? g_rr[c] : 0.f;
        }
        __syncthreads();

        float S[4][4];
#pragma unroll
        for (int a = 0; a < 4; a++)
#pragma unroll
            for (int j = 0; j < 4; j++) S[a][j] = 0.f;
#pragma unroll
        for (int d = 0; d < 64; d++) {
            float4 q4 = *(const float4*)&qst[d*36 + ty*4];
            float4 k4 = *(const float4*)&kst[d*68 + tx*4];
            float qa[4] = {q4.x, q4.y, q4.z, q4.w};
            float kb[4] = {k4.x, k4.y, k4.z, k4.w};
#pragma unroll
            for (int a = 0; a < 4; a++)
#pragma unroll
                for (int j = 0; j < 4; j++) S[a][j] += qa[a]*kb[j];
        }

#pragma unroll
        for (int a = 0; a < 4; a++) {
            int ii = ty*4 + a;
            int i  = i0 + ii;
            const float* qrrow = &g_qr[(size_t)(rbase + i)*QR_STRIDE + (j0 - i + 1024)];
#pragma unroll
            for (int bj = 0; bj < 4; bj++) {
                int jj = tx*4 + bj;
                int j  = j0 + jj;
                if (j <= i) {
                    float s = S[a][bj];
                    s += qrrow[jj];
                    s += rks[jj*128 + (ii - jj + 63)];
                    s += rrs[ii - jj + 63];
                    S[a][bj] = s * 0.125f;
                } else {
                    S[a][bj] = -1e30f;
                }
            }
        }

#pragma unroll
        for (int a = 0; a < 4; a++) {
            float rm = fmaxf(fmaxf(S[a][0], S[a][1]), fmaxf(S[a][2], S[a][3]));
#pragma unroll
            for (int msk = 1; msk < 16; msk <<= 1)
                rm = fmaxf(rm, __shfl_xor_sync(0xffffffffu, rm, msk));
            float mnew = fmaxf(m[a], rm);
            float corr = __expf(m[a] - mnew);
            float rs = 0.f;
#pragma unroll
            for (int bj = 0; bj < 4; bj++) {
                float p = __expf(S[a][bj] - mnew);
                S[a][bj] = p;
                rs += p;
            }
#pragma unroll
            for (int msk = 1; msk < 16; msk <<= 1)
                rs += __shfl_xor_sync(0xffffffffu, rs, msk);
            l[a] = l[a]*corr + rs;
            m[a] = mnew;
#pragma unroll
            for (int d = 0; d < 4; d++) O[a][d] *= corr;
        }

#pragma unroll
        for (int a = 0; a < 4; a++)
            *(float4*)&ps[(ty*4 + a)*68 + tx*4] =
                make_float4(S[a][0], S[a][1], S[a][2], S[a][3]);
        __syncthreads();

#pragma unroll
        for (int jj = 0; jj < 64; jj++) {
            float4 v4 = *(const float4*)&vs[jj*64 + tx*4];
#pragma unroll
            for (int a = 0; a < 4; a++) {
                float p = ps[(ty*4 + a)*68 + jj];
                O[a][0] += p*v4.x; O[a][1] += p*v4.y;
                O[a][2] += p*v4.z; O[a][3] += p*v4.w;
            }
        }
    }

#pragma unroll
    for (int a = 0; a < 4; a++) {
        float inv = 1.f / l[a];
        int i = i0 + ty*4 + a;
        *(float4*)&out[(size_t)(rbase + i)*HS + tx*4] =
            make_float4(O[a][0]*inv, O[a][1]*inv, O[a][2]*inv, O[a][3]*inv);
    }
}

// ============================================================
extern "C" void kernel_launch(void* const* d_in, const int* in_sizes, int n_in,
                              void* d_out, int out_size)
{
    const float* x   = (const float*)d_in[0];
    const float* Wk  = (const float*)d_in[1];
    const float* bk  = (const float*)d_in[2];
    const float* Wq  = (const float*)d_in[3];
    const float* bq  = (const float*)d_in[4];
    const float* Wv  = (const float*)d_in[5];
    const float* rel = (const float*)d_in[6];
    float* out = (float*)d_out;

    static int attr_done = 0;
    if (!attr_done) {
        cudaFuncSetAttribute(proj_mma_kernel,
                             cudaFuncAttributeMaxDynamicSharedMemorySize, PROJ_SMEM_BYTES);
        cudaFuncSetAttribute(relgemm_mma_kernel,
                             cudaFuncAttributeMaxDynamicSharedMemorySize, QRK_SMEM_BYTES);
        cudaFuncSetAttribute(attn_kernel,
                             cudaFuncAttributeMaxDynamicSharedMemorySize,
                             ATTN_SMEM_FLOATS * (int)sizeof(float));
        attr_done = 1;
    }

    wsplit_kernel<<<768, 256>>>(Wk, Wq, Wv);
    relsplit_kernel<<<513, 256>>>(rel);
    rr_kernel<<<4, 256>>>(rel);
    proj_mma_kernel<<<dim3(128, 3), 128, PROJ_SMEM_BYTES>>>(x, bk, bq);
    relgemm_mma_kernel<<<dim3(64, 9), 256, QRK_SMEM_BYTES>>>(0);
    relgemm_mma_kernel<<<dim3(64, 8), 256, QRK_SMEM_BYTES>>>(1);
    attn_kernel<<<BB*32, 128, ATTN_SMEM_FLOATS*sizeof(float)>>>(out);
}

// round 4
// speedup vs baseline: 1.4009x; 1.0050x over previous
#include <cuda_runtime.h>
#include <cuda_bf16.h>
#include <cstdint>

#define BB 8
#define TT 1024
#define DM 1024
#define HS 64
#define NROWS (BB*TT)        // 8192
#define QR_STRIDE 1028
#define MAXREL 1024

// -------- scratch (static device arrays; no runtime allocation) --------
__device__ float g_q[NROWS*HS];
__device__ float g_k[NROWS*HS];
__device__ float g_v[NROWS*HS];
__device__ float g_qr[(size_t)NROWS*QR_STRIDE + 256];  // pad: attn prefetch over-reads
__device__ float g_rk[(size_t)NROWS*MAXREL];
__device__ float g_rr[MAXREL];
__device__ __nv_bfloat16 g_qs[NROWS*128];      // q split: [row][0:64)=hi, [64:128)=lo
__device__ __nv_bfloat16 g_ks[NROWS*128];      // k split
__device__ __nv_bfloat16 g_rels[2049*128];     // rel split: [p][0:64)=hi, [64:128)=lo
__device__ __nv_bfloat16 g_wt[3*64*2048];      // W^T split: [o][n][0:1024)=hi, [1024:2048)=lo

// ============================================================
// helpers
// ============================================================
__device__ __forceinline__ uint32_t smem_to_u32(const void* p) {
    uint32_t a;
    asm("{ .reg .u64 tmp; cvta.to.shared.u64 tmp, %1; cvt.u32.u64 %0, tmp; }"
        : "=r"(a) : "l"(p));
    return a;
}
__device__ __forceinline__ void ldsm4(uint32_t& r0, uint32_t& r1, uint32_t& r2,
                                      uint32_t& r3, uint32_t addr) {
    asm volatile("ldmatrix.sync.aligned.m8n8.x4.shared.b16 {%0,%1,%2,%3}, [%4];"
        : "=r"(r0), "=r"(r1), "=r"(r2), "=r"(r3) : "r"(addr));
}
__device__ __forceinline__ void mma16816(float* c, const uint32_t* a,
                                         uint32_t b0, uint32_t b1) {
    asm volatile(
        "mma.sync.aligned.m16n8k16.row.col.f32.bf16.bf16.f32 "
        "{%0,%1,%2,%3}, {%4,%5,%6,%7}, {%8,%9}, {%0,%1,%2,%3};"
        : "+f"(c[0]), "+f"(c[1]), "+f"(c[2]), "+f"(c[3])
        : "r"(a[0]), "r"(a[1]), "r"(a[2]), "r"(a[3]), "r"(b0), "r"(b1));
}
__device__ __forceinline__ void split2(float v, __nv_bfloat16& h, __nv_bfloat16& l) {
    h = __float2bfloat16(v);
    l = __float2bfloat16(v - __bfloat162float(h));
}
__device__ __forceinline__ uint32_t pack2(__nv_bfloat16 a, __nv_bfloat16 b) {
    __nv_bfloat162 t; t.x = a; t.y = b;
    return *reinterpret_cast<uint32_t*>(&t);
}

// ============================================================
// Conversion kernels
// ============================================================
__global__ void wsplit_kernel(const float* __restrict__ Wk,
                              const float* __restrict__ Wq,
                              const float* __restrict__ Wv)
{
    int idx = blockIdx.x * 256 + threadIdx.x;
    if (idx >= 3*1024*64) return;
    int o = idx >> 16;
    int r = idx & 65535;
    int kk = r >> 6, n = r & 63;
    const float* W = (o == 0) ? Wk : (o == 1 ? Wq : Wv);
    float v = W[kk*64 + n];
    __nv_bfloat16 h, l; split2(v, h, l);
    g_wt[o*131072 + n*2048 + kk]        = h;
    g_wt[o*131072 + n*2048 + 1024 + kk] = l;
}

__global__ void relsplit_kernel(const float* __restrict__ rel)
{
    int idx = blockIdx.x * 256 + threadIdx.x;
    if (idx >= 2049*64) return;
    int p = idx >> 6, d = idx & 63;
    float v = rel[(size_t)p*64 + d];
    __nv_bfloat16 h, l; split2(v, h, l);
    g_rels[p*128 + d]      = h;
    g_rels[p*128 + 64 + d] = l;
}

__global__ void rr_kernel(const float* __restrict__ rel)
{
    int d = blockIdx.x * 256 + threadIdx.x;
    if (d < MAXREL) {
        const float* a = rel + (size_t)(1024 + d) * HS;
        const float* b = rel + (size_t)(1024 - d) * HS;
        float s = 0.f;
#pragma unroll
        for (int h = 0; h < HS; h++) s += a[h] * b[h];
        g_rr[d] = s;
    }
}

// ============================================================
// Fused projection GEMM: out[:, 0:64]=k, [64:128)=q, [128:192)=v
// grid (128 rowtiles, 2 col-halves), 128 threads, CTA tile 64x96.
// Register-prefetch of next x chunk hides LDG latency under mma.
// ============================================================
#define PROJ_SMEM_BYTES (2*64*72*2 + 2*96*72*2)   // 46080
__global__ __launch_bounds__(128) void proj_mma_kernel(
    const float* __restrict__ x,
    const float* __restrict__ bk, const float* __restrict__ bq)
{
    extern __shared__ char smc[];
    __nv_bfloat16* Ah = (__nv_bfloat16*)smc;        // [64][72]
    __nv_bfloat16* Al = Ah + 64*72;
    __nv_bfloat16* Bh = Al + 64*72;                 // [96][72]
    __nv_bfloat16* Bl = Bh + 96*72;
    uint32_t sb = smem_to_u32(smc);
    const uint32_t sAh = sb, sAl = sb + 9216, sBh = sb + 18432, sBl = sb + 32256;

    int tid = threadIdx.x, wid = tid >> 5, lane = tid & 31;
    int r0 = blockIdx.x * 64;
    int h  = blockIdx.y;                 // column half: cols h*96 .. h*96+95
    int wm = wid >> 1, wn = wid & 1;     // 2x2 warp grid, warp tile 32x48

    float c[2][6][4];
#pragma unroll
    for (int mt = 0; mt < 2; mt++)
#pragma unroll
        for (int nt = 0; nt < 6; nt++)
#pragma unroll
            for (int e = 0; e < 4; e++) c[mt][nt][e] = 0.f;

    int lr   = lane & 15;
    int lca  = (lane >> 4) << 3;
    int brow = (lane & 7) + ((lane >> 4) << 3);
    int bcol = (lane & 8) ? 8 : 0;

    // preload chunk 0 of x into registers
    float2 xr[16];
#pragma unroll
    for (int i = 0; i < 16; i++) {
        int idx = tid + i*128;
        int row = idx >> 5, kp = idx & 31;
        xr[i] = *(const float2*)&x[(size_t)(r0+row)*1024 + kp*2];
    }

    for (int ch = 0; ch < 16; ch++) {
        int k0 = ch * 64;
        // convert prefetched x -> smem (hi/lo)
#pragma unroll
        for (int i = 0; i < 16; i++) {
            int idx = tid + i*128;
            int row = idx >> 5, kp = idx & 31;
            __nv_bfloat16 h0,l0,h1,l1;
            split2(xr[i].x,h0,l0); split2(xr[i].y,h1,l1);
            *(uint32_t*)&Ah[row*72 + kp*2] = pack2(h0,h1);
            *(uint32_t*)&Al[row*72 + kp*2] = pack2(l0,l1);
        }
        // stage W^T chunk: 96 cols x 32 u32
#pragma unroll
        for (int i = 0; i < 24; i++) {
            int idx = tid + i*128;
            int n = idx >> 5, kp = idx & 31;
            int gc = h*96 + n;
            const __nv_bfloat16* base = g_wt + (size_t)(gc >> 6)*131072 + (size_t)(gc & 63)*2048;
            *(uint32_t*)&Bh[n*72 + kp*2] = *(const uint32_t*)&base[k0 + kp*2];
            *(uint32_t*)&Bl[n*72 + kp*2] = *(const uint32_t*)&base[1024 + k0 + kp*2];
        }
        __syncthreads();

        // prefetch next chunk's x (hidden behind the mma work below)
        if (ch < 15) {
#pragma unroll
            for (int i = 0; i < 16; i++) {
                int idx = tid + i*128;
                int row = idx >> 5, kp = idx & 31;
                xr[i] = *(const float2*)&x[(size_t)(r0+row)*1024 + k0 + 64 + kp*2];
            }
        }

#pragma unroll
        for (int ks = 0; ks < 4; ks++) {
            int kk = ks * 16;
            uint32_t ah[2][4], al[2][4];
#pragma unroll
            for (int mt = 0; mt < 2; mt++) {
                uint32_t ar = (uint32_t)((wm*32 + mt*16 + lr)*72 + kk + lca) * 2;
                ldsm4(ah[mt][0],ah[mt][1],ah[mt][2],ah[mt][3], sAh + ar);
                ldsm4(al[mt][0],al[mt][1],al[mt][2],al[mt][3], sAl + ar);
            }
#pragma unroll
            for (int p = 0; p < 3; p++) {
                uint32_t br = (uint32_t)((wn*48 + p*16 + brow)*72 + kk + bcol) * 2;
                uint32_t bh[4], bl[4];
                ldsm4(bh[0],bh[1],bh[2],bh[3], sBh + br);
                ldsm4(bl[0],bl[1],bl[2],bl[3], sBl + br);
#pragma unroll
                for (int mt = 0; mt < 2; mt++) {
                    mma16816(c[mt][2*p],   ah[mt], bh[0], bh[1]);
                    mma16816(c[mt][2*p+1], ah[mt], bh[2], bh[3]);
                    mma16816(c[mt][2*p],   al[mt], bh[0], bh[1]);
                    mma16816(c[mt][2*p+1], al[mt], bh[2], bh[3]);
                    mma16816(c[mt][2*p],   ah[mt], bl[0], bl[1]);
                    mma16816(c[mt][2*p+1], ah[mt], bl[2], bl[3]);
                }
            }
        }
        __syncthreads();
    }

    // ---- epilogue: stage to smem, coalesced stores + split write ----
    float* Cs = (float*)smc;   // [64][100] = 25.6KB
    int g = lane >> 2, lc2 = (lane & 3)*2;
#pragma unroll
    for (int mt = 0; mt < 2; mt++)
#pragma unroll
        for (int nt = 0; nt < 6; nt++) {
            int rrow = wm*32 + mt*16 + g;
            int col  = wn*48 + nt*8 + lc2;
            *(float2*)&Cs[rrow*100 + col]     = make_float2(c[mt][nt][0], c[mt][nt][1]);
            *(float2*)&Cs[(rrow+8)*100 + col] = make_float2(c[mt][nt][2], c[mt][nt][3]);
        }
    __syncthreads();
#pragma unroll
    for (int i = 0; i < 48; i++) {
        int idx = tid + i*128;          // 64 rows x 96 cols
        int row = idx / 96, col = idx - row*96;
        int gc = h*96 + col;
        int o = gc >> 6, cn = gc & 63;
        float v = Cs[row*100 + col];
        if (o == 0) v += bk[cn];
        else if (o == 1) v += bq[cn];
        size_t grow = (size_t)(r0 + row);
        if (o == 0) {
            g_k[grow*64 + cn] = v;
            __nv_bfloat16 hh, ll; split2(v, hh, ll);
            g_ks[grow*128 + cn] = hh; g_ks[grow*128 + 64 + cn] = ll;
        } else if (o == 1) {
            g_q[grow*64 + cn] = v;
            __nv_bfloat16 hh, ll; split2(v, hh, ll);
            g_qs[grow*128 + cn] = hh; g_qs[grow*128 + 64 + cn] = ll;
        } else {
            g_v[grow*64 + cn] = v;
        }
    }
}

// ============================================================
// QR / RK GEMM (mma.sync bf16 split), pre-scaled by 0.125,
// rr folded into QR. grid (64 rowtiles, 9|8 coltiles) trimmed,
// 256 threads, CTA 128x128, K=64.
// ============================================================
#define QRK_SMEM_BYTES (4*128*72*2)    // 73728
__global__ __launch_bounds__(256) void relgemm_mma_kernel(int mode)
{
    int r0 = blockIdx.x * 128;
    int i0 = r0 & (TT - 1);
    int p0 = blockIdx.y * 128;
    if (mode == 0) { if (p0 + 127 < 1024 - (i0 + 127)) return; }
    else           { if (p0 > 1023 - i0) return; }

    extern __shared__ char smc[];
    __nv_bfloat16* Ah = (__nv_bfloat16*)smc;        // [128][72]
    __nv_bfloat16* Al = Ah + 128*72;
    __nv_bfloat16* Bh = Al + 128*72;
    __nv_bfloat16* Bl = Bh + 128*72;
    uint32_t sb = smem_to_u32(smc);
    const uint32_t sAh = sb, sAl = sb + 128*72*2, sBh = sb + 2*128*72*2, sBl = sb + 3*128*72*2;

    int tid = threadIdx.x, wid = tid >> 5, lane = tid & 31;
    const __nv_bfloat16* A = mode ? g_ks : g_qs;
    const __nv_bfloat16* R = g_rels + (mode ? 1024*128 : 0);

    int wm = wid >> 2, wn = wid & 3;   // 2x4 warp grid, 64x32 warp tile

    float c[4][4][4];
#pragma unroll
    for (int mt = 0; mt < 4; mt++)
#pragma unroll
        for (int nt = 0; nt < 4; nt++)
#pragma unroll
            for (int e = 0; e < 4; e++) c[mt][nt][e] = 0.f;

#pragma unroll
    for (int i = 0; i < 16; i++) {
        int idx = tid + i*256;
        int row = idx >> 5, kp = idx & 31;
        *(uint32_t*)&Ah[row*72 + kp*2] = *(const uint32_t*)&A[(size_t)(r0+row)*128 + kp*2];
        *(uint32_t*)&Al[row*72 + kp*2] = *(const uint32_t*)&A[(size_t)(r0+row)*128 + 64 + kp*2];
        *(uint32_t*)&Bh[row*72 + kp*2] = *(const uint32_t*)&R[(size_t)(p0+row)*128 + kp*2];
        *(uint32_t*)&Bl[row*72 + kp*2] = *(const uint32_t*)&R[(size_t)(p0+row)*128 + 64 + kp*2];
    }
    __syncthreads();

    int lr   = lane & 15;
    int lca  = (lane >> 4) << 3;
    int brow = (lane & 7) + ((lane >> 4) << 3);
    int bcol = (lane & 8) ? 8 : 0;

#pragma unroll
    for (int ks = 0; ks < 4; ks++) {
        int kk = ks * 16;
        uint32_t ah[4][4], al[4][4];
#pragma unroll
        for (int mt = 0; mt < 4; mt++) {
            uint32_t ar = (uint32_t)((wm*64 + mt*16 + lr)*72 + kk + lca) * 2;
            ldsm4(ah[mt][0],ah[mt][1],ah[mt][2],ah[mt][3], sAh + ar);
            ldsm4(al[mt][0],al[mt][1],al[mt][2],al[mt][3], sAl + ar);
        }
#pragma unroll
        for (int p = 0; p < 2; p++) {
            uint32_t br = (uint32_t)((wn*32 + p*16 + brow)*72 + kk + bcol) * 2;
            uint32_t bh[4], bl[4];
            ldsm4(bh[0],bh[1],bh[2],bh[3], sBh + br);
            ldsm4(bl[0],bl[1],bl[2],bl[3], sBl + br);
#pragma unroll
            for (int mt = 0; mt < 4; mt++) {
                mma16816(c[mt][2*p],   ah[mt], bh[0], bh[1]);
                mma16816(c[mt][2*p+1], ah[mt], bh[2], bh[3]);
                mma16816(c[mt][2*p],   al[mt], bh[0], bh[1]);
                mma16816(c[mt][2*p+1], al[mt], bh[2], bh[3]);
                mma16816(c[mt][2*p],   ah[mt], bl[0], bl[1]);
                mma16816(c[mt][2*p+1], ah[mt], bl[2], bl[3]);
            }
        }
    }

    __syncthreads();
    float* Cs = (float*)smc;   // [128][132] = 67584 B
    int g = lane >> 2, lc2 = (lane & 3)*2;
#pragma unroll
    for (int mt = 0; mt < 4; mt++)
#pragma unroll
        for (int nt = 0; nt < 4; nt++) {
            int rrow = wm*64 + mt*16 + g;
            int col  = wn*32 + nt*8 + lc2;
            *(float2*)&Cs[rrow*132 + col]     = make_float2(c[mt][nt][0], c[mt][nt][1]);
            *(float2*)&Cs[(rrow+8)*132 + col] = make_float2(c[mt][nt][2], c[mt][nt][3]);
        }
    __syncthreads();

    int pmax = mode ? 1023 : 1024;
    float* outp = mode ? g_rk : g_qr;
    int ostride = mode ? 1024 : QR_STRIDE;
#pragma unroll
    for (int i = 0; i < 64; i++) {
        int idx = tid + i*256;
        int row = idx >> 7, cc = idx & 127;
        int p = p0 + cc;
        if (p <= pmax) {
            float v = Cs[row*132 + cc];
            if (mode == 0) v += g_rr[(1024 - p) & 1023];   // fold rr into qr
            outp[(size_t)(r0+row)*ostride + p] = v * 0.125f;
        }
    }
}

// ============================================================
// Causal flash attention. Q pre-scaled by 0.125; qr(+rr) and rk
// pre-scaled upstream. 32x64 tiles, 128 threads, longest-first.
// ============================================================
#define ATTN_SMEM_FLOATS (64*36 + 64*68 + 64*64 + 32*68 + 64*96)
__global__ __launch_bounds__(128) void attn_kernel(float* __restrict__ out)
{
    extern __shared__ float sm[];
    float* qst = sm;                 // [64][36] d-major Q (32 rows used)
    float* kst = qst + 64*36;        // [64][68] d-major K
    float* vs  = kst + 64*68;        // [64][64] row-major V
    float* ps  = vs  + 64*64;        // [32][68] probabilities
    float* rks = ps  + 32*68;        // [64][96] staged RK band

    int bid = blockIdx.x;
    int b  = bid >> 5;
    int it = 31 - (bid & 31);        // longest tiles first
    int i0 = it * 32;
    int rbase = b * TT;
    int tid = threadIdx.x, tx = tid & 15, ty = tid >> 4;

#pragma unroll
    for (int i = 0; i < 16; i++) {
        int idx = tid + i*128;
        int ii = idx >> 6, d = idx & 63;
        qst[d*36 + ii] = 0.125f * g_q[(size_t)(rbase + i0 + ii)*HS + d];
    }

    float m[4], l[4], O[4][4];
#pragma unroll
    for (int a = 0; a < 4; a++) {
        m[a] = -1e30f; l[a] = 0.f;
#pragma unroll
        for (int d = 0; d < 4; d++) O[a][d] = 0.f;
    }

    int jmax = it >> 1;
    for (int jt = 0; jt <= jmax; jt++) {
        int j0 = jt * 64;
        __syncthreads();
#pragma unroll
        for (int i = 0; i < 32; i++) {
            int idx = tid + i*128;
            int jj = idx >> 6, d = idx & 63;
            kst[d*68 + jj] = g_k[(size_t)(rbase + j0 + jj)*HS + d];
            vs[jj*64 + d]  = g_v[(size_t)(rbase + j0 + jj)*HS + d];
        }
        int cbase = i0 - j0 - 63;
#pragma unroll
        for (int i = 0; i < 48; i++) {
            int idx = tid + i*128;           // 64 x 96
            int jj = idx / 96, cc = idx - jj*96;
            int c = cbase + cc;
            float v = 0.f;
            if (cc < 95 && c >= 0 && c < MAXREL)
                v = g_rk[(size_t)(rbase + j0 + jj)*MAXREL + c];
            rks[jj*96 + cc] = v;
        }
        __syncthreads();

        // prefetch qr band into registers (latency hidden by QK below)
        float qrv[4][4];
#pragma unroll
        for (int a = 0; a < 4; a++) {
            int i = i0 + ty*4 + a;
            const float* qrrow = &g_qr[(size_t)(rbase + i)*QR_STRIDE + (j0 - i + 1024)];
#pragma unroll
            for (int bj = 0; bj < 4; bj++) qrv[a][bj] = qrrow[tx*4 + bj];
        }

        float S[4][4];
#pragma unroll
        for (int a = 0; a < 4; a++)
#pragma unroll
            for (int j = 0; j < 4; j++) S[a][j] = 0.f;
#pragma unroll
        for (int d = 0; d < 64; d++) {
            float4 q4 = *(const float4*)&qst[d*36 + ty*4];
            float4 k4 = *(const float4*)&kst[d*68 + tx*4];
            float qa[4] = {q4.x, q4.y, q4.z, q4.w};
            float kb[4] = {k4.x, k4.y, k4.z, k4.w};
#pragma unroll
            for (int a = 0; a < 4; a++)
#pragma unroll
                for (int j = 0; j < 4; j++) S[a][j] += qa[a]*kb[j];
        }

#pragma unroll
        for (int a = 0; a < 4; a++) {
            int ii = ty*4 + a;
            int i  = i0 + ii;
#pragma unroll
            for (int bj = 0; bj < 4; bj++) {
                int jj = tx*4 + bj;
                int j  = j0 + jj;
                if (j <= i)
                    S[a][bj] += qrv[a][bj] + rks[jj*96 + (ii - jj + 63)];
                else
                    S[a][bj] = -1e30f;
            }
        }

#pragma unroll
        for (int a = 0; a < 4; a++) {
            float rm = fmaxf(fmaxf(S[a][0], S[a][1]), fmaxf(S[a][2], S[a][3]));
#pragma unroll
            for (int msk = 1; msk < 16; msk <<= 1)
                rm = fmaxf(rm, __shfl_xor_sync(0xffffffffu, rm, msk));
            float mnew = fmaxf(m[a], rm);
            float corr = __expf(m[a] - mnew);
            float rs = 0.f;
#pragma unroll
            for (int bj = 0; bj < 4; bj++) {
                float p = __expf(S[a][bj] - mnew);
                S[a][bj] = p;
                rs += p;
            }
#pragma unroll
            for (int msk = 1; msk < 16; msk <<= 1)
                rs += __shfl_xor_sync(0xffffffffu, rs, msk);
            l[a] = l[a]*corr + rs;
            m[a] = mnew;
#pragma unroll
            for (int d = 0; d < 4; d++) O[a][d] *= corr;
        }

#pragma unroll
        for (int a = 0; a < 4; a++)
            *(float4*)&ps[(ty*4 + a)*68 + tx*4] =
                make_float4(S[a][0], S[a][1], S[a][2], S[a][3]);
        __syncthreads();

#pragma unroll
        for (int jj = 0; jj < 64; jj++) {
            float4 v4 = *(const float4*)&vs[jj*64 + tx*4];
#pragma unroll
            for (int a = 0; a < 4; a++) {
                float p = ps[(ty*4 + a)*68 + jj];
                O[a][0] += p*v4.x; O[a][1] += p*v4.y;
                O[a][2] += p*v4.z; O[a][3] += p*v4.w;
            }
        }
    }

#pragma unroll
    for (int a = 0; a < 4; a++) {
        float inv = 1.f / l[a];
        int i = i0 + ty*4 + a;
        *(float4*)&out[(size_t)(rbase + i)*HS + tx*4] =
            make_float4(O[a][0]*inv, O[a][1]*inv, O[a][2]*inv, O[a][3]*inv);
    }
}

// ============================================================
extern "C" void kernel_launch(void* const* d_in, const int* in_sizes, int n_in,
                              void* d_out, int out_size)
{
    const float* x   = (const float*)d_in[0];
    const float* Wk  = (const float*)d_in[1];
    const float* bk  = (const float*)d_in[2];
    const float* Wq  = (const float*)d_in[3];
    const float* bq  = (const float*)d_in[4];
    const float* Wv  = (const float*)d_in[5];
    const float* rel = (const float*)d_in[6];
    float* out = (float*)d_out;

    static int attr_done = 0;
    if (!attr_done) {
        cudaFuncSetAttribute(proj_mma_kernel,
                             cudaFuncAttributeMaxDynamicSharedMemorySize, PROJ_SMEM_BYTES);
        cudaFuncSetAttribute(relgemm_mma_kernel,
                             cudaFuncAttributeMaxDynamicSharedMemorySize, QRK_SMEM_BYTES);
        cudaFuncSetAttribute(attn_kernel,
                             cudaFuncAttributeMaxDynamicSharedMemorySize,
                             ATTN_SMEM_FLOATS * (int)sizeof(float));
        attr_done = 1;
    }

    wsplit_kernel<<<768, 256>>>(Wk, Wq, Wv);
    relsplit_kernel<<<513, 256>>>(rel);
    rr_kernel<<<4, 256>>>(rel);
    proj_mma_kernel<<<dim3(128, 2), 128, PROJ_SMEM_BYTES>>>(x, bk, bq);
    relgemm_mma_kernel<<<dim3(64, 9), 256, QRK_SMEM_BYTES>>>(0);
    relgemm_mma_kernel<<<dim3(64, 8), 256, QRK_SMEM_BYTES>>>(1);
    attn_kernel<<<BB*32, 128, ATTN_SMEM_FLOATS*sizeof(float)>>>(out);
}

// round 5
// speedup vs baseline: 2.0778x; 1.4832x over previous
#include <cuda_runtime.h>
#include <cuda_bf16.h>
#include <cstdint>

#define BB 8
#define TT 1024
#define DM 1024
#define HS 64
#define NROWS (BB*TT)        // 8192
#define QR_STRIDE 1028
#define MAXREL 1024

// -------- scratch (static device arrays; no runtime allocation) --------
__device__ float g_v[NROWS*HS];
__device__ float g_qr[(size_t)NROWS*QR_STRIDE + 256];  // pad: attn staging over-reads
__device__ float g_rk[(size_t)NROWS*MAXREL];
__device__ float g_rr[MAXREL];
__device__ __nv_bfloat16 g_qs[NROWS*128];      // q/8 split: [row][0:64)=hi,[64:128)=lo
__device__ __nv_bfloat16 g_ks[NROWS*128];      // k split
__device__ __nv_bfloat16 g_rels[2049*128];     // rel split
__device__ __nv_bfloat16 g_wt[3*64*2048];      // W^T split
__device__ __nv_bfloat16 g_vth[NROWS*HS];      // V^T hi: [(b*64+d)*1024 + t]
__device__ __nv_bfloat16 g_vtl[NROWS*HS];      // V^T lo
__device__ float g_po[2][(size_t)NROWS*HS];    // attention partials (unnormalized)
__device__ float g_pm[2][NROWS];
__device__ float g_pl[2][NROWS];

// ============================================================
// helpers
// ============================================================
__device__ __forceinline__ uint32_t smem_to_u32(const void* p) {
    uint32_t a;
    asm("{ .reg .u64 tmp; cvta.to.shared.u64 tmp, %1; cvt.u32.u64 %0, tmp; }"
        : "=r"(a) : "l"(p));
    return a;
}
__device__ __forceinline__ void ldsm4(uint32_t& r0, uint32_t& r1, uint32_t& r2,
                                      uint32_t& r3, uint32_t addr) {
    asm volatile("ldmatrix.sync.aligned.m8n8.x4.shared.b16 {%0,%1,%2,%3}, [%4];"
        : "=r"(r0), "=r"(r1), "=r"(r2), "=r"(r3) : "r"(addr));
}
__device__ __forceinline__ void mma16816(float* c, const uint32_t* a,
                                         uint32_t b0, uint32_t b1) {
    asm volatile(
        "mma.sync.aligned.m16n8k16.row.col.f32.bf16.bf16.f32 "
        "{%0,%1,%2,%3}, {%4,%5,%6,%7}, {%8,%9}, {%0,%1,%2,%3};"
        : "+f"(c[0]), "+f"(c[1]), "+f"(c[2]), "+f"(c[3])
        : "r"(a[0]), "r"(a[1]), "r"(a[2]), "r"(a[3]), "r"(b0), "r"(b1));
}
__device__ __forceinline__ void split2(float v, __nv_bfloat16& h, __nv_bfloat16& l) {
    h = __float2bfloat16(v);
    l = __float2bfloat16(v - __bfloat162float(h));
}
__device__ __forceinline__ uint32_t pack2(__nv_bfloat16 a, __nv_bfloat16 b) {
    __nv_bfloat162 t; t.x = a; t.y = b;
    return *reinterpret_cast<uint32_t*>(&t);
}

// ============================================================
// Conversion kernels
// ============================================================
__global__ void wsplit_kernel(const float* __restrict__ Wk,
                              const float* __restrict__ Wq,
                              const float* __restrict__ Wv)
{
    int idx = blockIdx.x * 256 + threadIdx.x;
    if (idx >= 3*1024*64) return;
    int o = idx >> 16;
    int r = idx & 65535;
    int kk = r >> 6, n = r & 63;
    const float* W = (o == 0) ? Wk : (o == 1 ? Wq : Wv);
    float v = W[kk*64 + n];
    __nv_bfloat16 h, l; split2(v, h, l);
    g_wt[o*131072 + n*2048 + kk]        = h;
    g_wt[o*131072 + n*2048 + 1024 + kk] = l;
}

__global__ void relsplit_kernel(const float* __restrict__ rel)
{
    int idx = blockIdx.x * 256 + threadIdx.x;
    if (idx >= 2049*64) return;
    int p = idx >> 6, d = idx & 63;
    float v = rel[(size_t)p*64 + d];
    __nv_bfloat16 h, l; split2(v, h, l);
    g_rels[p*128 + d]      = h;
    g_rels[p*128 + 64 + d] = l;
}

__global__ void rr_kernel(const float* __restrict__ rel)
{
    int d = blockIdx.x * 256 + threadIdx.x;
    if (d < MAXREL) {
        const float* a = rel + (size_t)(1024 + d) * HS;
        const float* b = rel + (size_t)(1024 - d) * HS;
        float s = 0.f;
#pragma unroll
        for (int h = 0; h < HS; h++) s += a[h] * b[h];
        g_rr[d] = s;
    }
}

// V transpose + split: g_v[b*1024+t][d] -> g_vth/g_vtl[(b*64+d)*1024+t]
__global__ __launch_bounds__(256) void vsplit_kernel()
{
    __shared__ float ts[64][65];
    int b = blockIdx.x >> 4;
    int t0 = (blockIdx.x & 15) * 64;
    int tid = threadIdx.x;
#pragma unroll
    for (int i = 0; i < 16; i++) {
        int idx = tid + i*256;
        int tl = idx >> 6, d = idx & 63;
        ts[tl][d] = g_v[(size_t)(b*1024 + t0 + tl)*64 + d];
    }
    __syncthreads();
#pragma unroll
    for (int i = 0; i < 16; i++) {
        int idx = tid + i*256;
        int d = idx >> 6, tl = idx & 63;
        float v = ts[tl][d];
        __nv_bfloat16 h, l; split2(v, h, l);
        g_vth[(size_t)(b*64 + d)*1024 + t0 + tl] = h;
        g_vtl[(size_t)(b*64 + d)*1024 + t0 + tl] = l;
    }
}

// ============================================================
// Fused projection GEMM (as round 4; epilogue writes split forms only)
// ============================================================
#define PROJ_SMEM_BYTES (2*64*72*2 + 2*96*72*2)   // 46080
__global__ __launch_bounds__(128) void proj_mma_kernel(
    const float* __restrict__ x,
    const float* __restrict__ bk, const float* __restrict__ bq)
{
    extern __shared__ char smc[];
    __nv_bfloat16* Ah = (__nv_bfloat16*)smc;        // [64][72]
    __nv_bfloat16* Al = Ah + 64*72;
    __nv_bfloat16* Bh = Al + 64*72;                 // [96][72]
    __nv_bfloat16* Bl = Bh + 96*72;
    uint32_t sb = smem_to_u32(smc);
    const uint32_t sAh = sb, sAl = sb + 9216, sBh = sb + 18432, sBl = sb + 32256;

    int tid = threadIdx.x, wid = tid >> 5, lane = tid & 31;
    int r0 = blockIdx.x * 64;
    int h  = blockIdx.y;
    int wm = wid >> 1, wn = wid & 1;

    float c[2][6][4];
#pragma unroll
    for (int mt = 0; mt < 2; mt++)
#pragma unroll
        for (int nt = 0; nt < 6; nt++)
#pragma unroll
            for (int e = 0; e < 4; e++) c[mt][nt][e] = 0.f;

    int lr   = lane & 15;
    int lca  = (lane >> 4) << 3;
    int brow = (lane & 7) + ((lane >> 4) << 3);
    int bcol = (lane & 8) ? 8 : 0;

    float2 xr[16];
#pragma unroll
    for (int i = 0; i < 16; i++) {
        int idx = tid + i*128;
        int row = idx >> 5, kp = idx & 31;
        xr[i] = *(const float2*)&x[(size_t)(r0+row)*1024 + kp*2];
    }

    for (int ch = 0; ch < 16; ch++) {
        int k0 = ch * 64;
#pragma unroll
        for (int i = 0; i < 16; i++) {
            int idx = tid + i*128;
            int row = idx >> 5, kp = idx & 31;
            __nv_bfloat16 h0,l0,h1,l1;
            split2(xr[i].x,h0,l0); split2(xr[i].y,h1,l1);
            *(uint32_t*)&Ah[row*72 + kp*2] = pack2(h0,h1);
            *(uint32_t*)&Al[row*72 + kp*2] = pack2(l0,l1);
        }
#pragma unroll
        for (int i = 0; i < 24; i++) {
            int idx = tid + i*128;
            int n = idx >> 5, kp = idx & 31;
            int gc = h*96 + n;
            const __nv_bfloat16* base = g_wt + (size_t)(gc >> 6)*131072 + (size_t)(gc & 63)*2048;
            *(uint32_t*)&Bh[n*72 + kp*2] = *(const uint32_t*)&base[k0 + kp*2];
            *(uint32_t*)&Bl[n*72 + kp*2] = *(const uint32_t*)&base[1024 + k0 + kp*2];
        }
        __syncthreads();

        if (ch < 15) {
#pragma unroll
            for (int i = 0; i < 16; i++) {
                int idx = tid + i*128;
                int row = idx >> 5, kp = idx & 31;
                xr[i] = *(const float2*)&x[(size_t)(r0+row)*1024 + k0 + 64 + kp*2];
            }
        }

#pragma unroll
        for (int ks = 0; ks < 4; ks++) {
            int kk = ks * 16;
            uint32_t ah[2][4], al[2][4];
#pragma unroll
            for (int mt = 0; mt < 2; mt++) {
                uint32_t ar = (uint32_t)((wm*32 + mt*16 + lr)*72 + kk + lca) * 2;
                ldsm4(ah[mt][0],ah[mt][1],ah[mt][2],ah[mt][3], sAh + ar);
                ldsm4(al[mt][0],al[mt][1],al[mt][2],al[mt][3], sAl + ar);
            }
#pragma unroll
            for (int p = 0; p < 3; p++) {
                uint32_t br = (uint32_t)((wn*48 + p*16 + brow)*72 + kk + bcol) * 2;
                uint32_t bh[4], bl[4];
                ldsm4(bh[0],bh[1],bh[2],bh[3], sBh + br);
                ldsm4(bl[0],bl[1],bl[2],bl[3], sBl + br);
#pragma unroll
                for (int mt = 0; mt < 2; mt++) {
                    mma16816(c[mt][2*p],   ah[mt], bh[0], bh[1]);
                    mma16816(c[mt][2*p+1], ah[mt], bh[2], bh[3]);
                    mma16816(c[mt][2*p],   al[mt], bh[0], bh[1]);
                    mma16816(c[mt][2*p+1], al[mt], bh[2], bh[3]);
                    mma16816(c[mt][2*p],   ah[mt], bl[0], bl[1]);
                    mma16816(c[mt][2*p+1], ah[mt], bl[2], bl[3]);
                }
            }
        }
        __syncthreads();
    }

    float* Cs = (float*)smc;   // [64][100]
    int g = lane >> 2, lc2 = (lane & 3)*2;
#pragma unroll
    for (int mt = 0; mt < 2; mt++)
#pragma unroll
        for (int nt = 0; nt < 6; nt++) {
            int rrow = wm*32 + mt*16 + g;
            int col  = wn*48 + nt*8 + lc2;
            *(float2*)&Cs[rrow*100 + col]     = make_float2(c[mt][nt][0], c[mt][nt][1]);
            *(float2*)&Cs[(rrow+8)*100 + col] = make_float2(c[mt][nt][2], c[mt][nt][3]);
        }
    __syncthreads();
#pragma unroll
    for (int i = 0; i < 48; i++) {
        int idx = tid + i*128;
        int row = idx / 96, col = idx - row*96;
        int gc = h*96 + col;
        int o = gc >> 6, cn = gc & 63;
        float v = Cs[row*100 + col];
        size_t grow = (size_t)(r0 + row);
        if (o == 0) {
            v += bk[cn];
            __nv_bfloat16 hh, ll; split2(v, hh, ll);
            g_ks[grow*128 + cn] = hh; g_ks[grow*128 + 64 + cn] = ll;
        } else if (o == 1) {
            v += bq[cn];
            __nv_bfloat16 hh, ll; split2(0.125f * v, hh, ll);   // pre-scale Q
            g_qs[grow*128 + cn] = hh; g_qs[grow*128 + 64 + cn] = ll;
        } else {
            g_v[grow*64 + cn] = v;
        }
    }
}

// ============================================================
// QR / RK GEMM. mode0 (QR): A=g_qs (already x0.125), +0.125*rr folded.
// mode1 (RK): A=g_ks, x0.125 in epilogue.
// ============================================================
#define QRK_SMEM_BYTES (4*128*72*2)    // 73728
__global__ __launch_bounds__(256) void relgemm_mma_kernel(int mode)
{
    int r0 = blockIdx.x * 128;
    int i0 = r0 & (TT - 1);
    int p0 = blockIdx.y * 128;
    if (mode == 0) { if (p0 + 127 < 1024 - (i0 + 127)) return; }
    else           { if (p0 > 1023 - i0) return; }

    extern __shared__ char smc[];
    __nv_bfloat16* Ah = (__nv_bfloat16*)smc;
    __nv_bfloat16* Al = Ah + 128*72;
    __nv_bfloat16* Bh = Al + 128*72;
    __nv_bfloat16* Bl = Bh + 128*72;
    uint32_t sb = smem_to_u32(smc);
    const uint32_t sAh = sb, sAl = sb + 128*72*2, sBh = sb + 2*128*72*2, sBl = sb + 3*128*72*2;

    int tid = threadIdx.x, wid = tid >> 5, lane = tid & 31;
    const __nv_bfloat16* A = mode ? g_ks : g_qs;
    const __nv_bfloat16* R = g_rels + (mode ? 1024*128 : 0);

    int wm = wid >> 2, wn = wid & 3;

    float c[4][4][4];
#pragma unroll
    for (int mt = 0; mt < 4; mt++)
#pragma unroll
        for (int nt = 0; nt < 4; nt++)
#pragma unroll
            for (int e = 0; e < 4; e++) c[mt][nt][e] = 0.f;

#pragma unroll
    for (int i = 0; i < 16; i++) {
        int idx = tid + i*256;
        int row = idx >> 5, kp = idx & 31;
        *(uint32_t*)&Ah[row*72 + kp*2] = *(const uint32_t*)&A[(size_t)(r0+row)*128 + kp*2];
        *(uint32_t*)&Al[row*72 + kp*2] = *(const uint32_t*)&A[(size_t)(r0+row)*128 + 64 + kp*2];
        *(uint32_t*)&Bh[row*72 + kp*2] = *(const uint32_t*)&R[(size_t)(p0+row)*128 + kp*2];
        *(uint32_t*)&Bl[row*72 + kp*2] = *(const uint32_t*)&R[(size_t)(p0+row)*128 + 64 + kp*2];
    }
    __syncthreads();

    int lr   = lane & 15;
    int lca  = (lane >> 4) << 3;
    int brow = (lane & 7) + ((lane >> 4) << 3);
    int bcol = (lane & 8) ? 8 : 0;

#pragma unroll
    for (int ks = 0; ks < 4; ks++) {
        int kk = ks * 16;
        uint32_t ah[4][4], al[4][4];
#pragma unroll
        for (int mt = 0; mt < 4; mt++) {
            uint32_t ar = (uint32_t)((wm*64 + mt*16 + lr)*72 + kk + lca) * 2;
            ldsm4(ah[mt][0],ah[mt][1],ah[mt][2],ah[mt][3], sAh + ar);
            ldsm4(al[mt][0],al[mt][1],al[mt][2],al[mt][3], sAl + ar);
        }
#pragma unroll
        for (int p = 0; p < 2; p++) {
            uint32_t br = (uint32_t)((wn*32 + p*16 + brow)*72 + kk + bcol) * 2;
            uint32_t bh[4], bl[4];
            ldsm4(bh[0],bh[1],bh[2],bh[3], sBh + br);
            ldsm4(bl[0],bl[1],bl[2],bl[3], sBl + br);
#pragma unroll
            for (int mt = 0; mt < 4; mt++) {
                mma16816(c[mt][2*p],   ah[mt], bh[0], bh[1]);
                mma16816(c[mt][2*p+1], ah[mt], bh[2], bh[3]);
                mma16816(c[mt][2*p],   al[mt], bh[0], bh[1]);
                mma16816(c[mt][2*p+1], al[mt], bh[2], bh[3]);
                mma16816(c[mt][2*p],   ah[mt], bl[0], bl[1]);
                mma16816(c[mt][2*p+1], ah[mt], bl[2], bl[3]);
            }
        }
    }

    __syncthreads();
    float* Cs = (float*)smc;
    int g = lane >> 2, lc2 = (lane & 3)*2;
#pragma unroll
    for (int mt = 0; mt < 4; mt++)
#pragma unroll
        for (int nt = 0; nt < 4; nt++) {
            int rrow = wm*64 + mt*16 + g;
            int col  = wn*32 + nt*8 + lc2;
            *(float2*)&Cs[rrow*132 + col]     = make_float2(c[mt][nt][0], c[mt][nt][1]);
            *(float2*)&Cs[(rrow+8)*132 + col] = make_float2(c[mt][nt][2], c[mt][nt][3]);
        }
    __syncthreads();

    int pmax = mode ? 1023 : 1024;
    float* outp = mode ? g_rk : g_qr;
    int ostride = mode ? 1024 : QR_STRIDE;
#pragma unroll
    for (int i = 0; i < 64; i++) {
        int idx = tid + i*256;
        int row = idx >> 7, cc = idx & 127;
        int p = p0 + cc;
        if (p <= pmax) {
            float v = Cs[row*132 + cc];
            if (mode == 0) v += 0.125f * g_rr[(1024 - p) & 1023];
            else           v *= 0.125f;
            outp[(size_t)(r0+row)*ostride + p] = v;
        }
    }
}

// ============================================================
// MMA flash attention, split-j two-partial. 64x64 tiles, 128 thr.
// Writes unnormalized partials + (m,l) to scratch; merge_kernel finishes.
// ============================================================
#define ATTN_SMEM_BYTES 88832
__global__ __launch_bounds__(128) void attn_mma_kernel()
{
    extern __shared__ char smc[];
    const int OQH=0, OQL=9216, OKH=18432, OKL=27648, OVH=36864, OVL=46080;
    float* qrs = (float*)(smc + 55296);   // [64][66]
    float* rks = (float*)(smc + 72192);   // [64][65]
    uint32_t sb = smem_to_u32(smc);

    int bid = blockIdx.x;                 // 256 = 16 it x 8 b x 2 part
    int it   = 15 - (bid >> 4);           // longest first
    int b    = (bid >> 1) & 7;
    int part = bid & 1;
    int i0 = it * 64;
    int rbase = b * TT;

    int tid = threadIdx.x, wid = tid >> 5, lane = tid & 31;
    int m0r = wid * 16;
    int lr   = lane & 15;
    int lca  = (lane >> 4) << 3;
    int brow = (lane & 7) + ((lane >> 4) << 3);
    int bcol = (lane & 8) ? 8 : 0;
    int g  = lane >> 2;
    int t2 = (lane & 3) * 2;

    const uint32_t* qs32 = (const uint32_t*)g_qs;
    const uint32_t* ks32 = (const uint32_t*)g_ks;
    const uint32_t* vh32 = (const uint32_t*)g_vth;
    const uint32_t* vl32 = (const uint32_t*)g_vtl;

    // stage Q tile once
#pragma unroll
    for (int i = 0; i < 16; i++) {
        int idx = tid + i*128;
        int row = idx >> 5, kp = idx & 31;
        size_t base = (size_t)(rbase + i0 + row) * 64;
        *(uint32_t*)(smc + OQH + row*144 + kp*4) = qs32[base + kp];
        *(uint32_t*)(smc + OQL + row*144 + kp*4) = qs32[base + 32 + kp];
    }

    float O[8][4];
#pragma unroll
    for (int nf = 0; nf < 8; nf++)
#pragma unroll
        for (int e = 0; e < 4; e++) O[nf][e] = 0.f;
    float m2[2] = {-1e30f, -1e30f};
    float l2[2] = {0.f, 0.f};

    for (int jt = part; jt <= it; jt += 2) {
        int j0 = jt * 64;
        __syncthreads();

        // ---- stage K, V, qr, rk ----
#pragma unroll
        for (int i = 0; i < 16; i++) {
            int idx = tid + i*128;
            int row = idx >> 5, kp = idx & 31;
            size_t base = (size_t)(rbase + j0 + row) * 64;
            *(uint32_t*)(smc + OKH + row*144 + kp*4) = ks32[base + kp];
            *(uint32_t*)(smc + OKL + row*144 + kp*4) = ks32[base + 32 + kp];
            size_t vbase = ((size_t)(b*64 + row) << 9) + (j0 >> 1);
            *(uint32_t*)(smc + OVH + row*144 + kp*4) = vh32[vbase + kp];
            *(uint32_t*)(smc + OVL + row*144 + kp*4) = vl32[vbase + kp];
        }
#pragma unroll
        for (int i = 0; i < 32; i++) {
            int idx = tid + i*128;
            int r = idx >> 6, cc = idx & 63;
            int ii = i0 + r;
            qrs[r*66 + cc] = g_qr[(size_t)(rbase + ii)*QR_STRIDE + (j0 + cc - ii + 1024)];
        }
#pragma unroll
        for (int i = 0; i < 32; i++) {
            int idx = tid + i*128;
            int cc = idx >> 6, r = idx & 63;
            int c = i0 + r - j0 - cc;
            rks[cc*65 + r] = (c >= 0) ? g_rk[(size_t)(rbase + j0 + cc)*1024 + c] : 0.f;
        }
        __syncthreads();

        // ---- S = Q K^T (3-pass split) ----
        float S[8][4];
#pragma unroll
        for (int nf = 0; nf < 8; nf++)
#pragma unroll
            for (int e = 0; e < 4; e++) S[nf][e] = 0.f;
#pragma unroll
        for (int ks = 0; ks < 4; ks++) {
            int kk = ks * 16;
            uint32_t aoff = (uint32_t)((m0r + lr)*72 + kk + lca) * 2;
            uint32_t ah[4], al[4];
            ldsm4(ah[0],ah[1],ah[2],ah[3], sb + OQH + aoff);
            ldsm4(al[0],al[1],al[2],al[3], sb + OQL + aoff);
#pragma unroll
            for (int ng = 0; ng < 4; ng++) {
                uint32_t boff = (uint32_t)((ng*16 + brow)*72 + kk + bcol) * 2;
                uint32_t bh[4], bl[4];
                ldsm4(bh[0],bh[1],bh[2],bh[3], sb + OKH + boff);
                ldsm4(bl[0],bl[1],bl[2],bl[3], sb + OKL + boff);
                mma16816(S[2*ng],   ah, bh[0], bh[1]);
                mma16816(S[2*ng+1], ah, bh[2], bh[3]);
                mma16816(S[2*ng],   al, bh[0], bh[1]);
                mma16816(S[2*ng+1], al, bh[2], bh[3]);
                mma16816(S[2*ng],   ah, bl[0], bl[1]);
                mma16816(S[2*ng+1], ah, bl[2], bl[3]);
            }
        }

        // ---- biases + mask ----
        int r0g = m0r + g, r1g = r0g + 8;
#pragma unroll
        for (int nf = 0; nf < 8; nf++) {
            int cc0 = nf*8 + t2;
            S[nf][0] += qrs[r0g*66 + cc0]     + rks[cc0*65 + r0g];
            S[nf][1] += qrs[r0g*66 + cc0 + 1] + rks[(cc0+1)*65 + r0g];
            S[nf][2] += qrs[r1g*66 + cc0]     + rks[cc0*65 + r1g];
            S[nf][3] += qrs[r1g*66 + cc0 + 1] + rks[(cc0+1)*65 + r1g];
        }
        if (jt == it) {   // diagonal tile: mask j > i  (local: cc > r)
#pragma unroll
            for (int nf = 0; nf < 8; nf++) {
                int cc0 = nf*8 + t2;
                if (cc0     > r0g) S[nf][0] = -1e30f;
                if (cc0 + 1 > r0g) S[nf][1] = -1e30f;
                if (cc0     > r1g) S[nf][2] = -1e30f;
                if (cc0 + 1 > r1g) S[nf][3] = -1e30f;
            }
        }

        // ---- online softmax (rows g, g+8 of this warp's 16-row band) ----
        float mx0 = -1e30f, mx1 = -1e30f;
#pragma unroll
        for (int nf = 0; nf < 8; nf++) {
            mx0 = fmaxf(mx0, fmaxf(S[nf][0], S[nf][1]));
            mx1 = fmaxf(mx1, fmaxf(S[nf][2], S[nf][3]));
        }
        mx0 = fmaxf(mx0, __shfl_xor_sync(0xffffffffu, mx0, 1));
        mx0 = fmaxf(mx0, __shfl_xor_sync(0xffffffffu, mx0, 2));
        mx1 = fmaxf(mx1, __shfl_xor_sync(0xffffffffu, mx1, 1));
        mx1 = fmaxf(mx1, __shfl_xor_sync(0xffffffffu, mx1, 2));
        float mn0 = fmaxf(m2[0], mx0), mn1 = fmaxf(m2[1], mx1);
        float corr0 = __expf(m2[0] - mn0), corr1 = __expf(m2[1] - mn1);
        float rs0 = 0.f, rs1 = 0.f;
#pragma unroll
        for (int nf = 0; nf < 8; nf++) {
            S[nf][0] = __expf(S[nf][0] - mn0); rs0 += S[nf][0];
            S[nf][1] = __expf(S[nf][1] - mn0); rs0 += S[nf][1];
            S[nf][2] = __expf(S[nf][2] - mn1); rs1 += S[nf][2];
            S[nf][3] = __expf(S[nf][3] - mn1); rs1 += S[nf][3];
        }
        rs0 += __shfl_xor_sync(0xffffffffu, rs0, 1);
        rs0 += __shfl_xor_sync(0xffffffffu, rs0, 2);
        rs1 += __shfl_xor_sync(0xffffffffu, rs1, 1);
        rs1 += __shfl_xor_sync(0xffffffffu, rs1, 2);
        l2[0] = l2[0]*corr0 + rs0; m2[0] = mn0;
        l2[1] = l2[1]*corr1 + rs1; m2[1] = mn1;
#pragma unroll
        for (int nf = 0; nf < 8; nf++) {
            O[nf][0] *= corr0; O[nf][1] *= corr0;
            O[nf][2] *= corr1; O[nf][3] *= corr1;
        }

        // ---- O += P V (P from regs, split 2-pass x V split) ----
#pragma unroll
        for (int ks = 0; ks < 4; ks++) {
            int kk = ks * 16;
            float* Sa = S[2*ks];
            float* Sc = S[2*ks + 1];
            __nv_bfloat16 h0,h1,h2,h3,h4,h5,h6,h7;
            h0 = __float2bfloat16(Sa[0]); h1 = __float2bfloat16(Sa[1]);
            h2 = __float2bfloat16(Sa[2]); h3 = __float2bfloat16(Sa[3]);
            h4 = __float2bfloat16(Sc[0]); h5 = __float2bfloat16(Sc[1]);
            h6 = __float2bfloat16(Sc[2]); h7 = __float2bfloat16(Sc[3]);
            uint32_t ph[4], pl[4];
            ph[0] = pack2(h0, h1); ph[1] = pack2(h2, h3);
            ph[2] = pack2(h4, h5); ph[3] = pack2(h6, h7);
            pl[0] = pack2(__float2bfloat16(Sa[0]-__bfloat162float(h0)),
                          __float2bfloat16(Sa[1]-__bfloat162float(h1)));
            pl[1] = pack2(__float2bfloat16(Sa[2]-__bfloat162float(h2)),
                          __float2bfloat16(Sa[3]-__bfloat162float(h3)));
            pl[2] = pack2(__float2bfloat16(Sc[0]-__bfloat162float(h4)),
                          __float2bfloat16(Sc[1]-__bfloat162float(h5)));
            pl[3] = pack2(__float2bfloat16(Sc[2]-__bfloat162float(h6)),
                          __float2bfloat16(Sc[3]-__bfloat162float(h7)));
#pragma unroll
            for (int ng = 0; ng < 4; ng++) {
                uint32_t boff = (uint32_t)((ng*16 + brow)*72 + kk + bcol) * 2;
                uint32_t bh[4], bl[4];
                ldsm4(bh[0],bh[1],bh[2],bh[3], sb + OVH + boff);
                ldsm4(bl[0],bl[1],bl[2],bl[3], sb + OVL + boff);
                mma16816(O[2*ng],   ph, bh[0], bh[1]);
                mma16816(O[2*ng+1], ph, bh[2], bh[3]);
                mma16816(O[2*ng],   pl, bh[0], bh[1]);
                mma16816(O[2*ng+1], pl, bh[2], bh[3]);
                mma16816(O[2*ng],   ph, bl[0], bl[1]);
                mma16816(O[2*ng+1], ph, bl[2], bl[3]);
            }
        }
    }

    // ---- write partials ----
    int r0g = m0r + g;
    size_t rowA = (size_t)(rbase + i0 + r0g);
    size_t rowB = rowA + 8;
#pragma unroll
    for (int nf = 0; nf < 8; nf++) {
        int col = nf*8 + t2;
        *(float2*)&g_po[part][rowA*64 + col] = make_float2(O[nf][0], O[nf][1]);
        *(float2*)&g_po[part][rowB*64 + col] = make_float2(O[nf][2], O[nf][3]);
    }
    if ((lane & 3) == 0) {
        g_pm[part][rowA] = m2[0]; g_pl[part][rowA] = l2[0];
        g_pm[part][rowB] = m2[1]; g_pl[part][rowB] = l2[1];
    }
}

// ============================================================
// Merge the two partials into the final output.
// ============================================================
__global__ void merge_kernel(float* __restrict__ out)
{
    int idx = blockIdx.x * 256 + threadIdx.x;    // 524288
    int row = idx >> 6;
    float m0 = g_pm[0][row], m1 = g_pm[1][row];
    float l0 = g_pl[0][row], l1 = g_pl[1][row];
    float M  = fmaxf(m0, m1);
    float w0 = __expf(m0 - M), w1 = __expf(m1 - M);
    float denom = w0*l0 + w1*l1;
    out[idx] = (w0*g_po[0][idx] + w1*g_po[1][idx]) / denom;
}

// ============================================================
extern "C" void kernel_launch(void* const* d_in, const int* in_sizes, int n_in,
                              void* d_out, int out_size)
{
    const float* x   = (const float*)d_in[0];
    const float* Wk  = (const float*)d_in[1];
    const float* bk  = (const float*)d_in[2];
    const float* Wq  = (const float*)d_in[3];
    const float* bq  = (const float*)d_in[4];
    const float* Wv  = (const float*)d_in[5];
    const float* rel = (const float*)d_in[6];
    float* out = (float*)d_out;

    static int attr_done = 0;
    if (!attr_done) {
        cudaFuncSetAttribute(proj_mma_kernel,
                             cudaFuncAttributeMaxDynamicSharedMemorySize, PROJ_SMEM_BYTES);
        cudaFuncSetAttribute(relgemm_mma_kernel,
                             cudaFuncAttributeMaxDynamicSharedMemorySize, QRK_SMEM_BYTES);
        cudaFuncSetAttribute(attn_mma_kernel,
                             cudaFuncAttributeMaxDynamicSharedMemorySize, ATTN_SMEM_BYTES);
        attr_done = 1;
    }

    wsplit_kernel<<<768, 256>>>(Wk, Wq, Wv);
    relsplit_kernel<<<513, 256>>>(rel);
    rr_kernel<<<4, 256>>>(rel);
    proj_mma_kernel<<<dim3(128, 2), 128, PROJ_SMEM_BYTES>>>(x, bk, bq);
    vsplit_kernel<<<128, 256>>>();
    relgemm_mma_kernel<<<dim3(64, 9), 256, QRK_SMEM_BYTES>>>(0);
    relgemm_mma_kernel<<<dim3(64, 8), 256, QRK_SMEM_BYTES>>>(1);
    attn_mma_kernel<<<256, 128, ATTN_SMEM_BYTES>>>();
    merge_kernel<<<2048, 256>>>(out);
}